// round 6
// baseline (speedup 1.0000x reference)
#include <cuda_runtime.h>

#define D       256
#define L       50
#define BSZ     4096
#define JP      4                    // K-dim split factor
#define JW      (D / 4 / JP)         // 16 j4-steps per part
#define BMG     16                   // batches per partial-gemm block
#define BMR     8                    // batches per reduce block

// Repacked weights as 4x4 tiles: float idx ((j4*4 + r)*64 + tc)*4 + cc
//   where i = tc*4 + r (output channel), j = j4*4 + cc (k index)
__device__ float g_w1p[D * D];
__device__ float g_w2p[D * D];
// Gather outputs: 64 float4 channels per batch (8 MB total)
__device__ float4 g_tq [BSZ * (D / 4)];
__device__ float4 g_tsv[BSZ * (D / 4)];
// Partial GEMV results [part][batch][channel] (16 MB each)
__device__ float g_pq[JP * BSZ * D];
__device__ float g_ps[JP * BSZ * D];

#define FMA2(acc, a, b)  asm("fma.rn.f32x2 %0, %1, %2, %0;" : "+l"(acc) : "l"(a), "l"(b))
#define UNPACK2(x, y, u) asm("mov.b64 {%0, %1}, %2;" : "=f"(x), "=f"(y) : "l"(u))

__device__ __forceinline__ float fsigmoid(float x) {
    return 1.0f / (1.0f + __expf(-x));
}

// ------------- Kernel 1: ragged gather-sum (one block/batch) + weight repack -
__global__ void __launch_bounds__(256) gather_kernel(
    const int*   __restrict__ acts_req,
    const int*   __restrict__ acts_slot,
    const int*   __restrict__ acts_val,
    const float* __restrict__ w1,
    const float* __restrict__ w2,
    const float* __restrict__ emb)
{
    __shared__ int idx[3 * L + 2];
    __shared__ __align__(16) float4 redq [4][D / 4];
    __shared__ __align__(16) float4 redsv[4][D / 4];

    const int b   = blockIdx.x;
    const int tid = threadIdx.x;

    // Fold weight repack into the first 256 blocks (gemm launches after us)
    if (b < D) {
        int i = b, j = tid;
        float v1 = w1[i * D + j];
        float v2 = w2[i * D + j];
        int o = (((j >> 2) * 4 + (i & 3)) * 64 + (i >> 2)) * 4 + (j & 3);
        g_w1p[o] = v1;
        g_w2p[o] = v2;
    }

    if (tid < 3 * L) {
        int v;
        if      (tid < L)     v = acts_req [b * L + tid];
        else if (tid < 2 * L) v = acts_slot[b * L + (tid - L)];
        else                  v = acts_val [b * L + (tid - 2 * L)];
        idx[tid] = v;
    }
    __syncthreads();

    const float4* __restrict__ emb4 = (const float4*)emb;
    const int p    = tid >> 6;
    const int lane = tid & 63;

    float4 q0 = make_float4(0.f,0.f,0.f,0.f), q1 = q0, s0 = q0, s1 = q0;

    #pragma unroll
    for (int k = 0; k < 13; k++) {
        int l = p + 4 * k;
        if (l < L) {
            float4 e = emb4[(size_t)idx[l] * (D / 4) + lane];
            if (k & 1) { q1.x += e.x; q1.y += e.y; q1.z += e.z; q1.w += e.w; }
            else       { q0.x += e.x; q0.y += e.y; q0.z += e.z; q0.w += e.w; }
        }
    }
    #pragma unroll
    for (int k = 0; k < 25; k++) {
        int l = L + p + 4 * k;
        if (l < 3 * L) {
            float4 e = emb4[(size_t)idx[l] * (D / 4) + lane];
            if (k & 1) { s1.x += e.x; s1.y += e.y; s1.z += e.z; s1.w += e.w; }
            else       { s0.x += e.x; s0.y += e.y; s0.z += e.z; s0.w += e.w; }
        }
    }

    redq [p][lane] = make_float4(q0.x+q1.x, q0.y+q1.y, q0.z+q1.z, q0.w+q1.w);
    redsv[p][lane] = make_float4(s0.x+s1.x, s0.y+s1.y, s0.z+s1.z, s0.w+s1.w);
    __syncthreads();

    if (tid < 64) {
        float4 a = redq[0][tid], c = redq[1][tid], d = redq[2][tid], e = redq[3][tid];
        g_tq[b * (D / 4) + tid] =
            make_float4(a.x+c.x+d.x+e.x, a.y+c.y+d.y+e.y, a.z+c.z+d.z+e.z, a.w+c.w+d.w+e.w);
    } else if (tid < 128) {
        int ln = tid - 64;
        float4 a = redsv[0][ln], c = redsv[1][ln], d = redsv[2][ln], e = redsv[3][ln];
        g_tsv[b * (D / 4) + ln] =
            make_float4(a.x+c.x+d.x+e.x, a.y+c.y+d.y+e.y, a.z+c.z+d.z+e.z, a.w+c.w+d.w+e.w);
    }
}

// ------------- Kernel 2a: K-split partial GEMV, 4x4 register tiles ----------
// Thread (tc, tb): channels tc*4..tc*4+3, batches tb*4..tb*4+3 (within group).
__global__ void __launch_bounds__(256) partial_gemm(void)
{
    __shared__ __align__(16) ulonglong2 tq_sm [BMG * JW];  // 4 KB
    __shared__ __align__(16) ulonglong2 tsv_sm[BMG * JW];  // 4 KB

    const int tid = threadIdx.x;
    const int jp  = blockIdx.x & (JP - 1);
    const int b0  = (blockIdx.x >> 2) * BMG;
    const int j0  = jp * JW;                 // in j4 units
    const int tc  = tid & 63;
    const int tb  = tid >> 6;

    // stage t chunks (256 entries, exactly one per thread)
    {
        int b = tid >> 4, jl = tid & (JW - 1);
        const ulonglong2* tq2  = (const ulonglong2*)g_tq;
        const ulonglong2* tsv2 = (const ulonglong2*)g_tsv;
        tq_sm [b * JW + jl] = tq2 [(b0 + b) * (D / 4) + j0 + jl];
        tsv_sm[b * JW + jl] = tsv2[(b0 + b) * (D / 4) + j0 + jl];
    }
    __syncthreads();

    // ---- pass 1: partial g_q = w1-part @ t_q ----
    {
        unsigned long long acc[4][4];   // [r][bb], lanes = j parity pairs
        #pragma unroll
        for (int r = 0; r < 4; r++)
            #pragma unroll
            for (int bb = 0; bb < 4; bb++) acc[r][bb] = 0ull;

        const ulonglong2* __restrict__ wv = (const ulonglong2*)g_w1p;
        #pragma unroll 4
        for (int jl = 0; jl < JW; jl++) {
            ulonglong2 w[4];
            #pragma unroll
            for (int r = 0; r < 4; r++)
                w[r] = wv[((j0 + jl) * 4 + r) * 64 + tc];   // coalesced LDG.128
            ulonglong2 t[4];
            #pragma unroll
            for (int bb = 0; bb < 4; bb++)
                t[bb] = tq_sm[(tb * 4 + bb) * JW + jl];     // broadcast LDS.128
            #pragma unroll
            for (int r = 0; r < 4; r++)
                #pragma unroll
                for (int bb = 0; bb < 4; bb++) {
                    FMA2(acc[r][bb], w[r].x, t[bb].x);
                    FMA2(acc[r][bb], w[r].y, t[bb].y);
                }
        }
        #pragma unroll
        for (int bb = 0; bb < 4; bb++) {
            float lo, hi; float4 o;
            UNPACK2(lo, hi, acc[0][bb]); o.x = lo + hi;
            UNPACK2(lo, hi, acc[1][bb]); o.y = lo + hi;
            UNPACK2(lo, hi, acc[2][bb]); o.z = lo + hi;
            UNPACK2(lo, hi, acc[3][bb]); o.w = lo + hi;
            *(float4*)&g_pq[((size_t)jp * BSZ + b0 + tb * 4 + bb) * D + tc * 4] = o;
        }
    }

    // ---- pass 2: partial g_sv = w2-part @ t_sv ----
    {
        unsigned long long acc[4][4];
        #pragma unroll
        for (int r = 0; r < 4; r++)
            #pragma unroll
            for (int bb = 0; bb < 4; bb++) acc[r][bb] = 0ull;

        const ulonglong2* __restrict__ wv = (const ulonglong2*)g_w2p;
        #pragma unroll 4
        for (int jl = 0; jl < JW; jl++) {
            ulonglong2 w[4];
            #pragma unroll
            for (int r = 0; r < 4; r++)
                w[r] = wv[((j0 + jl) * 4 + r) * 64 + tc];
            ulonglong2 t[4];
            #pragma unroll
            for (int bb = 0; bb < 4; bb++)
                t[bb] = tsv_sm[(tb * 4 + bb) * JW + jl];
            #pragma unroll
            for (int r = 0; r < 4; r++)
                #pragma unroll
                for (int bb = 0; bb < 4; bb++) {
                    FMA2(acc[r][bb], w[r].x, t[bb].x);
                    FMA2(acc[r][bb], w[r].y, t[bb].y);
                }
        }
        #pragma unroll
        for (int bb = 0; bb < 4; bb++) {
            float lo, hi; float4 o;
            UNPACK2(lo, hi, acc[0][bb]); o.x = lo + hi;
            UNPACK2(lo, hi, acc[1][bb]); o.y = lo + hi;
            UNPACK2(lo, hi, acc[2][bb]); o.z = lo + hi;
            UNPACK2(lo, hi, acc[3][bb]); o.w = lo + hi;
            *(float4*)&g_ps[((size_t)jp * BSZ + b0 + tb * 4 + bb) * D + tc * 4] = o;
        }
    }
}

// ------------- Kernel 2b: reduce partials + gate epilogue, 512 blocks -------
__global__ void __launch_bounds__(256) reduce_gate(
    const int*   __restrict__ slot_names,
    const float* __restrict__ emb,
    float*       __restrict__ out)
{
    __shared__ int sidx[BMR * 4];

    const int tid = threadIdx.x;
    const int b0  = blockIdx.x * BMR;

    if (tid < BMR * 4) sidx[tid] = slot_names[b0 * 4 + tid];
    __syncthreads();

    const int i = tid;
    #pragma unroll
    for (int b = 0; b < BMR; b++) {
        const size_t base = (size_t)(b0 + b) * D + i;
        float gq = 0.f, gs = 0.f;
        #pragma unroll
        for (int p = 0; p < JP; p++) {
            gq += g_pq[(size_t)p * BSZ * D + base];
            gs += g_ps[(size_t)p * BSZ * D + base];
        }
        const size_t ob = ((size_t)(b0 + b)) * 4;
        #pragma unroll
        for (int sl = 0; sl < 4; sl++) {
            int row = sidx[b * 4 + sl];
            float c = emb[(size_t)row * D + i];
            out[(ob + sl) * D + i] = c + fsigmoid(c * gq) + fsigmoid(c * gs);
        }
    }
}

extern "C" void kernel_launch(void* const* d_in, const int* in_sizes, int n_in,
                              void* d_out, int out_size)
{
    const int*   acts_req   = (const int*)  d_in[0];
    const int*   acts_slot  = (const int*)  d_in[1];
    const int*   acts_val   = (const int*)  d_in[2];
    const int*   slot_names = (const int*)  d_in[3];
    const float* emb        = (const float*)d_in[4];
    const float* w1         = (const float*)d_in[5];
    const float* w2         = (const float*)d_in[6];
    float*       out        = (float*)d_out;

    gather_kernel<<<BSZ, 256>>>(acts_req, acts_slot, acts_val, w1, w2, emb);
    partial_gemm<<<(BSZ / BMG) * JP, 256>>>();
    reduce_gate<<<BSZ / BMR, 256>>>(slot_names, emb, out);
}

// round 7
// speedup vs baseline: 1.4264x; 1.4264x over previous
#include <cuda_runtime.h>

#define D       256
#define L       50
#define BSZ     4096
#define JP      4                    // K-dim split factor
#define JW      (D / 4 / JP)         // 16 j4-steps per part
#define BMG     16                   // batches per partial-gemm block

// Repacked transposed weights: ulonglong2 at [j4*D + i] = {w[i][4j4..4j4+3]}
__device__ float g_w1p[D * D];
__device__ float g_w2p[D * D];
// Gather outputs: 64 float4 channels per batch (8 MB total)
__device__ float4 g_tq [BSZ * (D / 4)];
__device__ float4 g_tsv[BSZ * (D / 4)];
// Partial GEMV results [part][batch][channel] (16 MB each)
__device__ float g_pq[JP * BSZ * D];
__device__ float g_ps[JP * BSZ * D];

#define FMA2(acc, a, b)  asm("fma.rn.f32x2 %0, %1, %2, %0;" : "+l"(acc) : "l"(a), "l"(b))
#define UNPACK2(x, y, u) asm("mov.b64 {%0, %1}, %2;" : "=f"(x), "=f"(y) : "l"(u))

__device__ __forceinline__ float fsigmoid(float x) {
    return 1.0f / (1.0f + __expf(-x));
}

// ------------- Kernel 1: ragged gather-sum (one block/batch) + weight repack -
__global__ void __launch_bounds__(256) gather_kernel(
    const int*   __restrict__ acts_req,
    const int*   __restrict__ acts_slot,
    const int*   __restrict__ acts_val,
    const float* __restrict__ w1,
    const float* __restrict__ w2,
    const float* __restrict__ emb)
{
    __shared__ int idx[3 * L + 2];
    __shared__ __align__(16) float4 redq [4][D / 4];
    __shared__ __align__(16) float4 redsv[4][D / 4];

    const int b   = blockIdx.x;
    const int tid = threadIdx.x;

    // Fold weight repack into the first 256 blocks (gemm launches after us)
    if (b < D) {
        int i = b, j = tid;
        float v1 = w1[i * D + j];
        float v2 = w2[i * D + j];
        int o = ((j >> 2) * D + i) * 4 + (j & 3);
        g_w1p[o] = v1;
        g_w2p[o] = v2;
    }

    if (tid < 3 * L) {
        int v;
        if      (tid < L)     v = acts_req [b * L + tid];
        else if (tid < 2 * L) v = acts_slot[b * L + (tid - L)];
        else                  v = acts_val [b * L + (tid - 2 * L)];
        idx[tid] = v;
    }
    __syncthreads();

    const float4* __restrict__ emb4 = (const float4*)emb;
    const int p    = tid >> 6;
    const int lane = tid & 63;

    float4 q0 = make_float4(0.f,0.f,0.f,0.f), q1 = q0, s0 = q0, s1 = q0;

    #pragma unroll
    for (int k = 0; k < 13; k++) {
        int l = p + 4 * k;
        if (l < L) {
            float4 e = emb4[(size_t)idx[l] * (D / 4) + lane];
            if (k & 1) { q1.x += e.x; q1.y += e.y; q1.z += e.z; q1.w += e.w; }
            else       { q0.x += e.x; q0.y += e.y; q0.z += e.z; q0.w += e.w; }
        }
    }
    #pragma unroll
    for (int k = 0; k < 25; k++) {
        int l = L + p + 4 * k;
        if (l < 3 * L) {
            float4 e = emb4[(size_t)idx[l] * (D / 4) + lane];
            if (k & 1) { s1.x += e.x; s1.y += e.y; s1.z += e.z; s1.w += e.w; }
            else       { s0.x += e.x; s0.y += e.y; s0.z += e.z; s0.w += e.w; }
        }
    }

    redq [p][lane] = make_float4(q0.x+q1.x, q0.y+q1.y, q0.z+q1.z, q0.w+q1.w);
    redsv[p][lane] = make_float4(s0.x+s1.x, s0.y+s1.y, s0.z+s1.z, s0.w+s1.w);
    __syncthreads();

    if (tid < 64) {
        float4 a = redq[0][tid], c = redq[1][tid], d = redq[2][tid], e = redq[3][tid];
        g_tq[b * (D / 4) + tid] =
            make_float4(a.x+c.x+d.x+e.x, a.y+c.y+d.y+e.y, a.z+c.z+d.z+e.z, a.w+c.w+d.w+e.w);
    } else if (tid < 128) {
        int ln = tid - 64;
        float4 a = redsv[0][ln], c = redsv[1][ln], d = redsv[2][ln], e = redsv[3][ln];
        g_tsv[b * (D / 4) + ln] =
            make_float4(a.x+c.x+d.x+e.x, a.y+c.y+d.y+e.y, a.z+c.z+d.z+e.z, a.w+c.w+d.w+e.w);
    }
}

// One K-split GEMV pass: chunk-4 prefetched w LDGs, broadcast t LDS, FMA2 math.
__device__ __forceinline__ void gemv_pass(
    const ulonglong2* __restrict__ wv,
    const ulonglong2* __restrict__ t_sm,
    int j0, int i, float* __restrict__ outp)
{
    unsigned long long acc[BMG];
    #pragma unroll
    for (int b = 0; b < BMG; b++) acc[b] = 0ull;

    #pragma unroll
    for (int jc = 0; jc < JW; jc += 4) {
        ulonglong2 w[4];
        #pragma unroll
        for (int u = 0; u < 4; u++)
            w[u] = wv[(j0 + jc + u) * D + i];        // 4 batched LDG.128 (MLP=4)
        #pragma unroll
        for (int u = 0; u < 4; u++) {
            #pragma unroll
            for (int b = 0; b < BMG; b++) {
                ulonglong2 t = t_sm[b * JW + jc + u]; // broadcast LDS.128
                FMA2(acc[b], w[u].x, t.x);
                FMA2(acc[b], w[u].y, t.y);
            }
        }
    }
    #pragma unroll
    for (int b = 0; b < BMG; b++) {
        float lo, hi; UNPACK2(lo, hi, acc[b]);
        outp[b * D] = lo + hi;                        // coalesced STG.32
    }
}

// ------------- Kernel 2a: K-split partial GEMV (f32x2), 1024 blocks ---------
__global__ void __launch_bounds__(256) partial_gemm(void)
{
    __shared__ __align__(16) ulonglong2 tq_sm [BMG * JW];  // 4 KB
    __shared__ __align__(16) ulonglong2 tsv_sm[BMG * JW];  // 4 KB

    const int tid = threadIdx.x;
    const int jp  = blockIdx.x & (JP - 1);
    const int b0  = (blockIdx.x >> 2) * BMG;
    const int j0  = jp * JW;

    // stage t chunks (256 entries, one per thread)
    {
        int b = tid >> 4, jl = tid & (JW - 1);
        const ulonglong2* tq2  = (const ulonglong2*)g_tq;
        const ulonglong2* tsv2 = (const ulonglong2*)g_tsv;
        tq_sm [b * JW + jl] = tq2 [(b0 + b) * (D / 4) + j0 + jl];
        tsv_sm[b * JW + jl] = tsv2[(b0 + b) * (D / 4) + j0 + jl];
    }
    __syncthreads();

    const int i = tid;
    gemv_pass((const ulonglong2*)g_w1p, tq_sm,  j0, i,
              &g_pq[((size_t)jp * BSZ + b0) * D + i]);
    gemv_pass((const ulonglong2*)g_w2p, tsv_sm, j0, i,
              &g_ps[((size_t)jp * BSZ + b0) * D + i]);
}

// ------------- Kernel 2b: reduce partials + gate epilogue, 1024 blocks ------
// Block = 4 batches x 64 channel-groups (float4 per thread).
__global__ void __launch_bounds__(256) reduce_gate(
    const int*   __restrict__ slot_names,
    const float* __restrict__ emb,
    float*       __restrict__ out)
{
    __shared__ int sidx[16];

    const int tid = threadIdx.x;
    const int b0  = blockIdx.x * 4;

    if (tid < 16) sidx[tid] = slot_names[b0 * 4 + tid];
    __syncthreads();

    const int tb = tid >> 6;         // batch within block
    const int tc = tid & 63;         // float4 channel group
    const int b  = b0 + tb;

    const float4* __restrict__ pq4 = (const float4*)g_pq;
    const float4* __restrict__ ps4 = (const float4*)g_ps;

    float4 gq = make_float4(0.f, 0.f, 0.f, 0.f), gs = gq;
    #pragma unroll
    for (int p = 0; p < JP; p++) {
        float4 a = pq4[((size_t)p * BSZ + b) * (D / 4) + tc];
        float4 c = ps4[((size_t)p * BSZ + b) * (D / 4) + tc];
        gq.x += a.x; gq.y += a.y; gq.z += a.z; gq.w += a.w;
        gs.x += c.x; gs.y += c.y; gs.z += c.z; gs.w += c.w;
    }

    const float4* __restrict__ emb4 = (const float4*)emb;
    float4* __restrict__ out4 = (float4*)out;
    #pragma unroll
    for (int sl = 0; sl < 4; sl++) {
        int row = sidx[tb * 4 + sl];
        float4 c = emb4[(size_t)row * (D / 4) + tc];
        float4 o;
        o.x = c.x + fsigmoid(c.x * gq.x) + fsigmoid(c.x * gs.x);
        o.y = c.y + fsigmoid(c.y * gq.y) + fsigmoid(c.y * gs.y);
        o.z = c.z + fsigmoid(c.z * gq.z) + fsigmoid(c.z * gs.z);
        o.w = c.w + fsigmoid(c.w * gq.w) + fsigmoid(c.w * gs.w);
        out4[((size_t)b * 4 + sl) * (D / 4) + tc] = o;
    }
}

extern "C" void kernel_launch(void* const* d_in, const int* in_sizes, int n_in,
                              void* d_out, int out_size)
{
    const int*   acts_req   = (const int*)  d_in[0];
    const int*   acts_slot  = (const int*)  d_in[1];
    const int*   acts_val   = (const int*)  d_in[2];
    const int*   slot_names = (const int*)  d_in[3];
    const float* emb        = (const float*)d_in[4];
    const float* w1         = (const float*)d_in[5];
    const float* w2         = (const float*)d_in[6];
    float*       out        = (float*)d_out;

    gather_kernel<<<BSZ, 256>>>(acts_req, acts_slot, acts_val, w1, w2, emb);
    partial_gemm<<<(BSZ / BMG) * JP, 256>>>();
    reduce_gate<<<BSZ / 4, 256>>>(slot_names, emb, out);
}